// round 4
// baseline (speedup 1.0000x reference)
#include <cuda_runtime.h>
#include <cuda_bf16.h>
#include <cstdint>
#include <math.h>

#define TOKS 1024
#define HDIM 1024
#define IDIM 1024
#define N2   2048   // 2*I
#define NEXP 16
#define TOPK 4

// ---------------- scratch (device globals; no allocations allowed) ----------
__device__ __nv_bfloat16 g_xn[TOKS * HDIM];                 // normalized tokens, bf16
__device__ float         g_gate[TOKS * TOPK];               // softmax gates per pair
__device__ int           g_cnt[NEXP];                       // tokens per expert
__device__ int           g_list[NEXP * TOKS];               // pairid = tok*4 + k
__device__ __nv_bfloat16 g_s[(size_t)NEXP * TOKS * IDIM];   // swiglu activations (32MB)
__device__ float         g_y[(size_t)TOKS * TOPK * HDIM];   // gated expert outputs (16MB)

__global__ void zero_cnt_kernel() {
    if (threadIdx.x < NEXP) g_cnt[threadIdx.x] = 0;
}

// ---------------- kernel 1: RMSNorm + router + top-4 ------------------------
__global__ __launch_bounds__(256) void router_kernel(
    const float* __restrict__ x, const float* __restrict__ nscale,
    const float* __restrict__ wg, const float* __restrict__ bg)
{
    __shared__ float xsh[HDIM];
    __shared__ float red[8];
    __shared__ float logits[NEXP];
    const int tok = blockIdx.x;
    const int tid = threadIdx.x;

    float4 v = ((const float4*)(x + (size_t)tok * HDIM))[tid];
    float ss = v.x*v.x + v.y*v.y + v.z*v.z + v.w*v.w;
    #pragma unroll
    for (int o = 16; o; o >>= 1) ss += __shfl_xor_sync(0xffffffffu, ss, o);
    if ((tid & 31) == 0) red[tid >> 5] = ss;
    __syncthreads();
    if (tid == 0) {
        float tot = 0.f;
        #pragma unroll
        for (int i = 0; i < 8; i++) tot += red[i];
        red[0] = tot;
    }
    __syncthreads();
    const float rms = rsqrtf(red[0] * (1.0f / HDIM) + 1e-5f);

    float4 sc = ((const float4*)nscale)[tid];
    float4 xn;
    xn.x = v.x * rms * sc.x; xn.y = v.y * rms * sc.y;
    xn.z = v.z * rms * sc.z; xn.w = v.w * rms * sc.w;
    xsh[tid*4+0] = xn.x; xsh[tid*4+1] = xn.y;
    xsh[tid*4+2] = xn.z; xsh[tid*4+3] = xn.w;
    __nv_bfloat162* xo = (__nv_bfloat162*)(g_xn + (size_t)tok * HDIM);
    xo[tid*2+0] = __floats2bfloat162_rn(xn.x, xn.y);
    xo[tid*2+1] = __floats2bfloat162_rn(xn.z, xn.w);
    __syncthreads();

    // router logits in exact fp32 (matches reference routing as closely as possible)
    const int warp = tid >> 5, lane = tid & 31;
    for (int e = warp; e < NEXP; e += 8) {
        float acc = 0.f;
        for (int i = lane; i < HDIM; i += 32)
            acc += xsh[i] * wg[i * NEXP + e];
        #pragma unroll
        for (int o = 16; o; o >>= 1) acc += __shfl_xor_sync(0xffffffffu, acc, o);
        if (lane == 0) logits[e] = acc + bg[e];
    }
    __syncthreads();

    if (tid == 0) {
        float lv[NEXP];
        #pragma unroll
        for (int e = 0; e < NEXP; e++) lv[e] = logits[e];
        float vals[TOPK]; int ids[TOPK];
        #pragma unroll
        for (int j = 0; j < TOPK; j++) {
            int bi = 0; float bv = lv[0];
            #pragma unroll
            for (int e2 = 1; e2 < NEXP; e2++)
                if (lv[e2] > bv) { bv = lv[e2]; bi = e2; }   // ties -> lowest index
            ids[j] = bi; vals[j] = bv; lv[bi] = -INFINITY;
        }
        float ex[TOPK]; float den = 0.f;
        #pragma unroll
        for (int j = 0; j < TOPK; j++) { ex[j] = expf(vals[j] - vals[0]); den += ex[j]; }
        const float rden = 1.f / den;
        #pragma unroll
        for (int j = 0; j < TOPK; j++) {
            const int pair = tok * TOPK + j;
            g_gate[pair] = ex[j] * rden;
            const int pos = atomicAdd(&g_cnt[ids[j]], 1);
            g_list[ids[j] * TOKS + pos] = pair;
        }
    }
}

// ---------------- mma helper -------------------------------------------------
__device__ __forceinline__ void mma_bf16(float c[4], const uint32_t a[4], const uint32_t b[2]) {
    asm volatile(
        "mma.sync.aligned.m16n8k16.row.col.f32.bf16.bf16.f32 "
        "{%0,%1,%2,%3},{%4,%5,%6,%7},{%8,%9},{%0,%1,%2,%3};\n"
        : "+f"(c[0]), "+f"(c[1]), "+f"(c[2]), "+f"(c[3])
        : "r"(a[0]), "r"(a[1]), "r"(a[2]), "r"(a[3]), "r"(b[0]), "r"(b[1]));
}

#define BM 64
#define BN 128
#define BK 32
#define SA 40   // smem strides (halves) -> conflict-free fragment loads
#define SB 40

// ---------------- kernel 2: grouped GEMM1 + bias + swiglu --------------------
__global__ __launch_bounds__(256) void gemm1_kernel(
    const float* __restrict__ w1, const float* __restrict__ b1)
{
    __shared__ __nv_bfloat16 Ash[BM * SA];
    __shared__ __nv_bfloat16 Bsh[BN * SB];   // transposed: [n][k]
    __shared__ int lsh[BM];

    const int e   = blockIdx.z;
    const int cnt = g_cnt[e];
    const int m0  = blockIdx.y * BM;
    if (m0 >= cnt) return;
    const int n0  = blockIdx.x * BN;
    const int tid = threadIdx.x;

    if (tid < BM) {
        const int p = m0 + tid;
        lsh[tid] = (p < cnt) ? g_list[e * TOKS + p] : 0;   // pad rows -> token 0 (safe read)
    }
    __syncthreads();

    const int arow = tid >> 2, akc = (tid & 3) * 8;
    const int tokA = lsh[arow] >> 2;
    const __nv_bfloat16* aptr = g_xn + (size_t)tokA * HDIM + akc;

    const int bkr = tid >> 3, bnc = (tid & 7) * 16;
    const float* bptr = w1 + ((size_t)e * HDIM + bkr) * N2 + n0 + bnc;

    const int warp = tid >> 5, lane = tid & 31;
    const int wm = warp & 1, wn = warp >> 1;

    float acc[2][4][4];
    #pragma unroll
    for (int i = 0; i < 2; i++)
        #pragma unroll
        for (int j = 0; j < 4; j++)
            #pragma unroll
            for (int q = 0; q < 4; q++) acc[i][j][q] = 0.f;

    uint4 aReg = *(const uint4*)(aptr);
    float4 b0r = *(const float4*)(bptr + 0);
    float4 b1r = *(const float4*)(bptr + 4);
    float4 b2r = *(const float4*)(bptr + 8);
    float4 b3r = *(const float4*)(bptr + 12);

    const int KT = HDIM / BK;
    for (int kt = 0; kt < KT; ++kt) {
        __syncthreads();
        *(uint4*)(&Ash[arow * SA + akc]) = aReg;
        Bsh[(bnc+ 0)*SB + bkr] = __float2bfloat16_rn(b0r.x);
        Bsh[(bnc+ 1)*SB + bkr] = __float2bfloat16_rn(b0r.y);
        Bsh[(bnc+ 2)*SB + bkr] = __float2bfloat16_rn(b0r.z);
        Bsh[(bnc+ 3)*SB + bkr] = __float2bfloat16_rn(b0r.w);
        Bsh[(bnc+ 4)*SB + bkr] = __float2bfloat16_rn(b1r.x);
        Bsh[(bnc+ 5)*SB + bkr] = __float2bfloat16_rn(b1r.y);
        Bsh[(bnc+ 6)*SB + bkr] = __float2bfloat16_rn(b1r.z);
        Bsh[(bnc+ 7)*SB + bkr] = __float2bfloat16_rn(b1r.w);
        Bsh[(bnc+ 8)*SB + bkr] = __float2bfloat16_rn(b2r.x);
        Bsh[(bnc+ 9)*SB + bkr] = __float2bfloat16_rn(b2r.y);
        Bsh[(bnc+10)*SB + bkr] = __float2bfloat16_rn(b2r.z);
        Bsh[(bnc+11)*SB + bkr] = __float2bfloat16_rn(b2r.w);
        Bsh[(bnc+12)*SB + bkr] = __float2bfloat16_rn(b3r.x);
        Bsh[(bnc+13)*SB + bkr] = __float2bfloat16_rn(b3r.y);
        Bsh[(bnc+14)*SB + bkr] = __float2bfloat16_rn(b3r.z);
        Bsh[(bnc+15)*SB + bkr] = __float2bfloat16_rn(b3r.w);
        __syncthreads();
        if (kt + 1 < KT) {
            aReg = *(const uint4*)(aptr + (size_t)(kt + 1) * BK);
            const float* bp = bptr + (size_t)(kt + 1) * BK * N2;
            b0r = *(const float4*)(bp + 0);
            b1r = *(const float4*)(bp + 4);
            b2r = *(const float4*)(bp + 8);
            b3r = *(const float4*)(bp + 12);
        }
        #pragma unroll
        for (int ks = 0; ks < BK; ks += 16) {
            const int r = lane >> 2, cc = (lane & 3) * 2;
            uint32_t afr[2][4];
            #pragma unroll
            for (int mi = 0; mi < 2; mi++) {
                const __nv_bfloat16* ap = &Ash[(wm*32 + mi*16 + r) * SA + ks + cc];
                afr[mi][0] = *(const uint32_t*)ap;
                afr[mi][1] = *(const uint32_t*)(ap + 8 * SA);
                afr[mi][2] = *(const uint32_t*)(ap + 8);
                afr[mi][3] = *(const uint32_t*)(ap + 8 * SA + 8);
            }
            uint32_t bfr[4][2];
            #pragma unroll
            for (int ni = 0; ni < 4; ni++) {
                const __nv_bfloat16* bp2 = &Bsh[(wn*32 + ni*8 + r) * SB + ks + cc];
                bfr[ni][0] = *(const uint32_t*)bp2;
                bfr[ni][1] = *(const uint32_t*)(bp2 + 8);
            }
            #pragma unroll
            for (int mi = 0; mi < 2; mi++)
                #pragma unroll
                for (int ni = 0; ni < 4; ni++)
                    mma_bf16(acc[mi][ni], afr[mi], bfr[ni]);
        }
    }

    // epilogue: bias + swiglu (even col = gate branch, odd col = linear branch)
    #pragma unroll
    for (int mi = 0; mi < 2; mi++) {
        #pragma unroll
        for (int ni = 0; ni < 4; ni++) {
            const int col = n0 + wn*32 + ni*8 + (lane & 3) * 2;   // even absolute h-col
            const float bb0 = b1[e * N2 + col];
            const float bb1 = b1[e * N2 + col + 1];
            #pragma unroll
            for (int half = 0; half < 2; half++) {
                const int lr  = wm*32 + mi*16 + (lane >> 2) + half*8;
                const int pos = m0 + lr;
                if (pos < cnt) {
                    const float h0 = acc[mi][ni][half*2 + 0] + bb0;
                    const float h1 = acc[mi][ni][half*2 + 1] + bb1;
                    const float a_ = fminf(h0, 7.0f);
                    const float b_ = fminf(fmaxf(h1, -7.0f), 7.0f);
                    const float sv = a_ * (1.0f / (1.0f + __expf(-1.702f * a_))) * (b_ + 1.0f);
                    g_s[((size_t)e * TOKS + pos) * IDIM + (col >> 1)] = __float2bfloat16_rn(sv);
                }
            }
        }
    }
}

// ---------------- kernel 3: grouped GEMM2 + bias + gate ----------------------
__global__ __launch_bounds__(256) void gemm2_kernel(
    const float* __restrict__ w2, const float* __restrict__ b2)
{
    __shared__ __nv_bfloat16 Ash[BM * SA];
    __shared__ __nv_bfloat16 Bsh[BN * SB];
    __shared__ int lsh[BM];

    const int e   = blockIdx.z;
    const int cnt = g_cnt[e];
    const int m0  = blockIdx.y * BM;
    if (m0 >= cnt) return;
    const int n0  = blockIdx.x * BN;
    const int tid = threadIdx.x;

    if (tid < BM) {
        const int p = m0 + tid;
        lsh[tid] = (p < cnt) ? g_list[e * TOKS + p] : 0;
    }
    __syncthreads();

    const int arow = tid >> 2, akc = (tid & 3) * 8;
    const __nv_bfloat16* aptr = g_s + ((size_t)e * TOKS + m0 + arow) * IDIM + akc;

    const int bkr = tid >> 3, bnc = (tid & 7) * 16;
    const float* bptr = w2 + ((size_t)e * IDIM + bkr) * HDIM + n0 + bnc;

    const int warp = tid >> 5, lane = tid & 31;
    const int wm = warp & 1, wn = warp >> 1;

    float acc[2][4][4];
    #pragma unroll
    for (int i = 0; i < 2; i++)
        #pragma unroll
        for (int j = 0; j < 4; j++)
            #pragma unroll
            for (int q = 0; q < 4; q++) acc[i][j][q] = 0.f;

    uint4 aReg = *(const uint4*)(aptr);
    float4 b0r = *(const float4*)(bptr + 0);
    float4 b1r = *(const float4*)(bptr + 4);
    float4 b2r = *(const float4*)(bptr + 8);
    float4 b3r = *(const float4*)(bptr + 12);

    const int KT = IDIM / BK;
    for (int kt = 0; kt < KT; ++kt) {
        __syncthreads();
        *(uint4*)(&Ash[arow * SA + akc]) = aReg;
        Bsh[(bnc+ 0)*SB + bkr] = __float2bfloat16_rn(b0r.x);
        Bsh[(bnc+ 1)*SB + bkr] = __float2bfloat16_rn(b0r.y);
        Bsh[(bnc+ 2)*SB + bkr] = __float2bfloat16_rn(b0r.z);
        Bsh[(bnc+ 3)*SB + bkr] = __float2bfloat16_rn(b0r.w);
        Bsh[(bnc+ 4)*SB + bkr] = __float2bfloat16_rn(b1r.x);
        Bsh[(bnc+ 5)*SB + bkr] = __float2bfloat16_rn(b1r.y);
        Bsh[(bnc+ 6)*SB + bkr] = __float2bfloat16_rn(b1r.z);
        Bsh[(bnc+ 7)*SB + bkr] = __float2bfloat16_rn(b1r.w);
        Bsh[(bnc+ 8)*SB + bkr] = __float2bfloat16_rn(b2r.x);
        Bsh[(bnc+ 9)*SB + bkr] = __float2bfloat16_rn(b2r.y);
        Bsh[(bnc+10)*SB + bkr] = __float2bfloat16_rn(b2r.z);
        Bsh[(bnc+11)*SB + bkr] = __float2bfloat16_rn(b2r.w);
        Bsh[(bnc+12)*SB + bkr] = __float2bfloat16_rn(b3r.x);
        Bsh[(bnc+13)*SB + bkr] = __float2bfloat16_rn(b3r.y);
        Bsh[(bnc+14)*SB + bkr] = __float2bfloat16_rn(b3r.z);
        Bsh[(bnc+15)*SB + bkr] = __float2bfloat16_rn(b3r.w);
        __syncthreads();
        if (kt + 1 < KT) {
            aReg = *(const uint4*)(aptr + (size_t)(kt + 1) * BK);
            const float* bp = bptr + (size_t)(kt + 1) * BK * HDIM;
            b0r = *(const float4*)(bp + 0);
            b1r = *(const float4*)(bp + 4);
            b2r = *(const float4*)(bp + 8);
            b3r = *(const float4*)(bp + 12);
        }
        #pragma unroll
        for (int ks = 0; ks < BK; ks += 16) {
            const int r = lane >> 2, cc = (lane & 3) * 2;
            uint32_t afr[2][4];
            #pragma unroll
            for (int mi = 0; mi < 2; mi++) {
                const __nv_bfloat16* ap = &Ash[(wm*32 + mi*16 + r) * SA + ks + cc];
                afr[mi][0] = *(const uint32_t*)ap;
                afr[mi][1] = *(const uint32_t*)(ap + 8 * SA);
                afr[mi][2] = *(const uint32_t*)(ap + 8);
                afr[mi][3] = *(const uint32_t*)(ap + 8 * SA + 8);
            }
            uint32_t bfr[4][2];
            #pragma unroll
            for (int ni = 0; ni < 4; ni++) {
                const __nv_bfloat16* bp2 = &Bsh[(wn*32 + ni*8 + r) * SB + ks + cc];
                bfr[ni][0] = *(const uint32_t*)bp2;
                bfr[ni][1] = *(const uint32_t*)(bp2 + 8);
            }
            #pragma unroll
            for (int mi = 0; mi < 2; mi++)
                #pragma unroll
                for (int ni = 0; ni < 4; ni++)
                    mma_bf16(acc[mi][ni], afr[mi], bfr[ni]);
        }
    }

    // epilogue: bias, gate, scatter to per-pair slot (deterministic combine later)
    #pragma unroll
    for (int mi = 0; mi < 2; mi++) {
        #pragma unroll
        for (int ni = 0; ni < 4; ni++) {
            const int col = n0 + wn*32 + ni*8 + (lane & 3) * 2;
            const float bb0 = b2[e * HDIM + col];
            const float bb1 = b2[e * HDIM + col + 1];
            #pragma unroll
            for (int half = 0; half < 2; half++) {
                const int lr  = wm*32 + mi*16 + (lane >> 2) + half*8;
                const int pos = m0 + lr;
                if (pos < cnt) {
                    const int pair = lsh[lr];
                    const float gate = g_gate[pair];
                    float2 o;
                    o.x = (acc[mi][ni][half*2 + 0] + bb0) * gate;
                    o.y = (acc[mi][ni][half*2 + 1] + bb1) * gate;
                    *(float2*)(g_y + (size_t)pair * HDIM + col) = o;
                }
            }
        }
    }
}

// ---------------- kernel 4: residual + combine -------------------------------
__global__ __launch_bounds__(256) void combine_kernel(
    const float* __restrict__ x, float* __restrict__ out)
{
    const int tok = blockIdx.x;
    const int tid = threadIdx.x;
    float4 o = ((const float4*)(x + (size_t)tok * HDIM))[tid];
    #pragma unroll
    for (int k = 0; k < TOPK; k++) {
        float4 yv = ((const float4*)(g_y + (size_t)(tok * TOPK + k) * HDIM))[tid];
        o.x += yv.x; o.y += yv.y; o.z += yv.z; o.w += yv.w;
    }
    ((float4*)(out + (size_t)tok * HDIM))[tid] = o;
}

// ---------------- launcher ---------------------------------------------------
extern "C" void kernel_launch(void* const* d_in, const int* in_sizes, int n_in,
                              void* d_out, int out_size)
{
    const float* x  = (const float*)d_in[0];
    const float* ns = (const float*)d_in[1];
    const float* wg = (const float*)d_in[2];
    const float* bg = (const float*)d_in[3];
    const float* w1 = (const float*)d_in[4];
    const float* b1 = (const float*)d_in[5];
    const float* w2 = (const float*)d_in[6];
    const float* b2 = (const float*)d_in[7];
    float* out = (float*)d_out;

    zero_cnt_kernel<<<1, 32>>>();
    router_kernel<<<TOKS, 256>>>(x, ns, wg, bg);
    gemm1_kernel<<<dim3(N2 / BN, TOKS / BM, NEXP), 256>>>(w1, b1);
    gemm2_kernel<<<dim3(HDIM / BN, TOKS / BM, NEXP), 256>>>(w2, b2);
    combine_kernel<<<TOKS, 256>>>(x, out);
}

// round 5
// speedup vs baseline: 1.5445x; 1.5445x over previous
#include <cuda_runtime.h>
#include <cuda_bf16.h>
#include <cstdint>
#include <math.h>

#define TOKS 1024
#define HDIM 1024
#define IDIM 1024
#define N2   2048   // 2*I
#define NEXP 16
#define TOPK 4

// ---------------- scratch (device globals; no allocations allowed) ----------
__device__ __nv_bfloat16 g_xn[TOKS * HDIM];                 // normalized tokens, bf16
__device__ float         g_gate[TOKS * TOPK];               // softmax gates per pair
__device__ int           g_cnt[NEXP];                       // tokens per expert
__device__ int           g_list[NEXP * TOKS];               // pairid = tok*4 + k
__device__ __nv_bfloat16 g_s[(size_t)NEXP * TOKS * IDIM];   // swiglu activations (32MB)
__device__ float         g_y[(size_t)TOKS * TOPK * HDIM];   // gated expert outputs (16MB)

__global__ void zero_cnt_kernel() {
    if (threadIdx.x < NEXP) g_cnt[threadIdx.x] = 0;
}

// ---------------- kernel 1: RMSNorm + router + top-4 ------------------------
__global__ __launch_bounds__(256) void router_kernel(
    const float* __restrict__ x, const float* __restrict__ nscale,
    const float* __restrict__ wg, const float* __restrict__ bg)
{
    __shared__ float xsh[HDIM];
    __shared__ float red[8];
    __shared__ float logits[NEXP];
    const int tok = blockIdx.x;
    const int tid = threadIdx.x;

    float4 v = ((const float4*)(x + (size_t)tok * HDIM))[tid];
    float ss = v.x*v.x + v.y*v.y + v.z*v.z + v.w*v.w;
    #pragma unroll
    for (int o = 16; o; o >>= 1) ss += __shfl_xor_sync(0xffffffffu, ss, o);
    if ((tid & 31) == 0) red[tid >> 5] = ss;
    __syncthreads();
    if (tid == 0) {
        float tot = 0.f;
        #pragma unroll
        for (int i = 0; i < 8; i++) tot += red[i];
        red[0] = tot;
    }
    __syncthreads();
    const float rms = rsqrtf(red[0] * (1.0f / HDIM) + 1e-5f);

    float4 sc = ((const float4*)nscale)[tid];
    float4 xn;
    xn.x = v.x * rms * sc.x; xn.y = v.y * rms * sc.y;
    xn.z = v.z * rms * sc.z; xn.w = v.w * rms * sc.w;
    xsh[tid*4+0] = xn.x; xsh[tid*4+1] = xn.y;
    xsh[tid*4+2] = xn.z; xsh[tid*4+3] = xn.w;
    __nv_bfloat162* xo = (__nv_bfloat162*)(g_xn + (size_t)tok * HDIM);
    xo[tid*2+0] = __floats2bfloat162_rn(xn.x, xn.y);
    xo[tid*2+1] = __floats2bfloat162_rn(xn.z, xn.w);
    __syncthreads();

    const int warp = tid >> 5, lane = tid & 31;
    for (int e = warp; e < NEXP; e += 8) {
        float acc = 0.f;
        for (int i = lane; i < HDIM; i += 32)
            acc += xsh[i] * wg[i * NEXP + e];
        #pragma unroll
        for (int o = 16; o; o >>= 1) acc += __shfl_xor_sync(0xffffffffu, acc, o);
        if (lane == 0) logits[e] = acc + bg[e];
    }
    __syncthreads();

    if (tid == 0) {
        float lv[NEXP];
        #pragma unroll
        for (int e = 0; e < NEXP; e++) lv[e] = logits[e];
        float vals[TOPK]; int ids[TOPK];
        #pragma unroll
        for (int j = 0; j < TOPK; j++) {
            int bi = 0; float bv = lv[0];
            #pragma unroll
            for (int e2 = 1; e2 < NEXP; e2++)
                if (lv[e2] > bv) { bv = lv[e2]; bi = e2; }   // ties -> lowest index
            ids[j] = bi; vals[j] = bv; lv[bi] = -INFINITY;
        }
        float ex[TOPK]; float den = 0.f;
        #pragma unroll
        for (int j = 0; j < TOPK; j++) { ex[j] = expf(vals[j] - vals[0]); den += ex[j]; }
        const float rden = 1.f / den;
        #pragma unroll
        for (int j = 0; j < TOPK; j++) {
            const int pair = tok * TOPK + j;
            g_gate[pair] = ex[j] * rden;
            const int pos = atomicAdd(&g_cnt[ids[j]], 1);
            g_list[ids[j] * TOKS + pos] = pair;
        }
    }
}

// ---------------- mma / ldmatrix helpers -------------------------------------
__device__ __forceinline__ void mma_bf16(float c[4], const uint32_t a[4], const uint32_t* b) {
    asm volatile(
        "mma.sync.aligned.m16n8k16.row.col.f32.bf16.bf16.f32 "
        "{%0,%1,%2,%3},{%4,%5,%6,%7},{%8,%9},{%0,%1,%2,%3};\n"
        : "+f"(c[0]), "+f"(c[1]), "+f"(c[2]), "+f"(c[3])
        : "r"(a[0]), "r"(a[1]), "r"(a[2]), "r"(a[3]), "r"(b[0]), "r"(b[1]));
}
__device__ __forceinline__ void ldsm_x4(uint32_t r[4], uint32_t addr) {
    asm volatile("ldmatrix.sync.aligned.m8n8.x4.shared.b16 {%0,%1,%2,%3}, [%4];\n"
        : "=r"(r[0]), "=r"(r[1]), "=r"(r[2]), "=r"(r[3]) : "r"(addr));
}
__device__ __forceinline__ void ldsm_x4_t(uint32_t r[4], uint32_t addr) {
    asm volatile("ldmatrix.sync.aligned.m8n8.x4.trans.shared.b16 {%0,%1,%2,%3}, [%4];\n"
        : "=r"(r[0]), "=r"(r[1]), "=r"(r[2]), "=r"(r[3]) : "r"(addr));
}
__device__ __forceinline__ uint32_t pack_bf16(float lo, float hi) {
    __nv_bfloat162 t = __floats2bfloat162_rn(lo, hi);
    return *(uint32_t*)&t;
}

#define BM 64
#define BN 128
#define BK 32
#define SA  40   // A smem stride (halves): row starts hit banks 0,20,8,28,... conflict-free
#define SBN 136  // B smem stride (halves): row starts hit banks 0,4,8,...,28 conflict-free

// core tile compute shared by both GEMMs; Ash is [BM][SA] row-major (m,k),
// Bsh is [BK][SBN] row-major (k,n).
#define GEMM_CORE(KT, A_NEXT, B_NEXT_PTR)                                       \
    uint4 aReg = *(const uint4*)(aptr);                                          \
    {                                                                            \
        const float4 f0 = *(const float4*)(bptr + 0);                            \
        const float4 f1 = *(const float4*)(bptr + 4);                            \
        const float4 f2 = *(const float4*)(bptr + 8);                            \
        const float4 f3 = *(const float4*)(bptr + 12);                           \
        bPack[0] = pack_bf16(f0.x, f0.y); bPack[1] = pack_bf16(f0.z, f0.w);      \
        bPack[2] = pack_bf16(f1.x, f1.y); bPack[3] = pack_bf16(f1.z, f1.w);      \
        bPack[4] = pack_bf16(f2.x, f2.y); bPack[5] = pack_bf16(f2.z, f2.w);      \
        bPack[6] = pack_bf16(f3.x, f3.y); bPack[7] = pack_bf16(f3.z, f3.w);      \
    }                                                                            \
    for (int kt = 0; kt < (KT); ++kt) {                                          \
        __syncthreads();                                                         \
        *(uint4*)(&Ash[arow * SA + akc]) = aReg;                                 \
        *(uint4*)(&Bsh[bkr * SBN + bnc]) = *(uint4*)(bPack);                     \
        *(uint4*)(&Bsh[bkr * SBN + bnc + 8]) = *(uint4*)(bPack + 4);             \
        __syncthreads();                                                         \
        if (kt + 1 < (KT)) {                                                     \
            aReg = *(const uint4*)(A_NEXT);                                      \
            const float* bp = (B_NEXT_PTR);                                      \
            const float4 f0 = *(const float4*)(bp + 0);                          \
            const float4 f1 = *(const float4*)(bp + 4);                          \
            const float4 f2 = *(const float4*)(bp + 8);                          \
            const float4 f3 = *(const float4*)(bp + 12);                         \
            bPack[0] = pack_bf16(f0.x, f0.y); bPack[1] = pack_bf16(f0.z, f0.w);  \
            bPack[2] = pack_bf16(f1.x, f1.y); bPack[3] = pack_bf16(f1.z, f1.w);  \
            bPack[4] = pack_bf16(f2.x, f2.y); bPack[5] = pack_bf16(f2.z, f2.w);  \
            bPack[6] = pack_bf16(f3.x, f3.y); bPack[7] = pack_bf16(f3.z, f3.w);  \
        }                                                                        \
        _Pragma("unroll")                                                        \
        for (int ks = 0; ks < BK; ks += 16) {                                    \
            uint32_t af0[4], af1[4], bf0[4], bf1[4];                             \
            ldsm_x4(af0, aFrag + (uint32_t)(ks * 2));                            \
            ldsm_x4(af1, aFrag + (uint32_t)((16 * SA + ks) * 2));                \
            ldsm_x4_t(bf0, bFrag + (uint32_t)(ks * SBN * 2));                    \
            ldsm_x4_t(bf1, bFrag + (uint32_t)((ks * SBN + 16) * 2));             \
            mma_bf16(acc[0][0], af0, bf0 + 0);                                   \
            mma_bf16(acc[0][1], af0, bf0 + 2);                                   \
            mma_bf16(acc[0][2], af0, bf1 + 0);                                   \
            mma_bf16(acc[0][3], af0, bf1 + 2);                                   \
            mma_bf16(acc[1][0], af1, bf0 + 0);                                   \
            mma_bf16(acc[1][1], af1, bf0 + 2);                                   \
            mma_bf16(acc[1][2], af1, bf1 + 0);                                   \
            mma_bf16(acc[1][3], af1, bf1 + 2);                                   \
        }                                                                        \
    }

// ---------------- kernel 2: grouped GEMM1 + bias + swiglu --------------------
__global__ __launch_bounds__(256) void gemm1_kernel(
    const float* __restrict__ w1, const float* __restrict__ b1)
{
    __shared__ __nv_bfloat16 Ash[BM * SA];
    __shared__ __nv_bfloat16 Bsh[BK * SBN];
    __shared__ int lsh[BM];

    const int e   = blockIdx.z;
    const int cnt = g_cnt[e];
    const int m0  = blockIdx.y * BM;
    if (m0 >= cnt) return;
    const int n0  = blockIdx.x * BN;
    const int tid = threadIdx.x;

    if (tid < BM) {
        const int p = m0 + tid;
        lsh[tid] = (p < cnt) ? g_list[e * TOKS + p] : 0;
    }
    __syncthreads();

    const int arow = tid >> 2, akc = (tid & 3) * 8;
    const int tokA = lsh[arow] >> 2;
    const __nv_bfloat16* aptr = g_xn + (size_t)tokA * HDIM + akc;

    const int bkr = tid >> 3, bnc = (tid & 7) * 16;
    const float* bptr = w1 + ((size_t)e * HDIM + bkr) * N2 + n0 + bnc;

    const int warp = tid >> 5, lane = tid & 31;
    const int wm = warp & 1, wn = warp >> 1;

    const uint32_t smA = (uint32_t)__cvta_generic_to_shared(Ash);
    const uint32_t smB = (uint32_t)__cvta_generic_to_shared(Bsh);
    const uint32_t aFrag = smA + (uint32_t)(((wm*32 + (lane & 15)) * SA + (lane >> 4) * 8) * 2);
    const uint32_t bFrag = smB + (uint32_t)(((lane & 15) * SBN + wn*32 + (lane >> 4) * 8) * 2);

    float acc[2][4][4];
    #pragma unroll
    for (int i = 0; i < 2; i++)
        #pragma unroll
        for (int j = 0; j < 4; j++)
            #pragma unroll
            for (int q = 0; q < 4; q++) acc[i][j][q] = 0.f;
    uint32_t bPack[8];

    GEMM_CORE(HDIM / BK,
              aptr + (size_t)(kt + 1) * BK,
              bptr + (size_t)(kt + 1) * BK * N2)

    // epilogue: bias + swiglu (even col = gate branch, odd col = linear branch)
    #pragma unroll
    for (int mi = 0; mi < 2; mi++) {
        #pragma unroll
        for (int ni = 0; ni < 4; ni++) {
            const int col = n0 + wn*32 + ni*8 + (lane & 3) * 2;
            const float bb0 = b1[e * N2 + col];
            const float bb1 = b1[e * N2 + col + 1];
            #pragma unroll
            for (int half = 0; half < 2; half++) {
                const int lr  = wm*32 + mi*16 + (lane >> 2) + half*8;
                const int pos = m0 + lr;
                if (pos < cnt) {
                    const float h0 = acc[mi][ni][half*2 + 0] + bb0;
                    const float h1 = acc[mi][ni][half*2 + 1] + bb1;
                    const float a_ = fminf(h0, 7.0f);
                    const float b_ = fminf(fmaxf(h1, -7.0f), 7.0f);
                    const float sv = a_ * (1.0f / (1.0f + __expf(-1.702f * a_))) * (b_ + 1.0f);
                    g_s[((size_t)e * TOKS + pos) * IDIM + (col >> 1)] = __float2bfloat16_rn(sv);
                }
            }
        }
    }
}

// ---------------- kernel 3: grouped GEMM2 + bias + gate ----------------------
__global__ __launch_bounds__(256) void gemm2_kernel(
    const float* __restrict__ w2, const float* __restrict__ b2)
{
    __shared__ __nv_bfloat16 Ash[BM * SA];
    __shared__ __nv_bfloat16 Bsh[BK * SBN];
    __shared__ int lsh[BM];

    const int e   = blockIdx.z;
    const int cnt = g_cnt[e];
    const int m0  = blockIdx.y * BM;
    if (m0 >= cnt) return;
    const int n0  = blockIdx.x * BN;
    const int tid = threadIdx.x;

    if (tid < BM) {
        const int p = m0 + tid;
        lsh[tid] = (p < cnt) ? g_list[e * TOKS + p] : 0;
    }
    __syncthreads();

    const int arow = tid >> 2, akc = (tid & 3) * 8;
    const __nv_bfloat16* aptr = g_s + ((size_t)e * TOKS + m0 + arow) * IDIM + akc;

    const int bkr = tid >> 3, bnc = (tid & 7) * 16;
    const float* bptr = w2 + ((size_t)e * IDIM + bkr) * HDIM + n0 + bnc;

    const int warp = tid >> 5, lane = tid & 31;
    const int wm = warp & 1, wn = warp >> 1;

    const uint32_t smA = (uint32_t)__cvta_generic_to_shared(Ash);
    const uint32_t smB = (uint32_t)__cvta_generic_to_shared(Bsh);
    const uint32_t aFrag = smA + (uint32_t)(((wm*32 + (lane & 15)) * SA + (lane >> 4) * 8) * 2);
    const uint32_t bFrag = smB + (uint32_t)(((lane & 15) * SBN + wn*32 + (lane >> 4) * 8) * 2);

    float acc[2][4][4];
    #pragma unroll
    for (int i = 0; i < 2; i++)
        #pragma unroll
        for (int j = 0; j < 4; j++)
            #pragma unroll
            for (int q = 0; q < 4; q++) acc[i][j][q] = 0.f;
    uint32_t bPack[8];

    GEMM_CORE(IDIM / BK,
              aptr + (size_t)(kt + 1) * BK,
              bptr + (size_t)(kt + 1) * BK * HDIM)

    // epilogue: bias, gate, scatter to per-pair slot (deterministic combine later)
    #pragma unroll
    for (int mi = 0; mi < 2; mi++) {
        #pragma unroll
        for (int ni = 0; ni < 4; ni++) {
            const int col = n0 + wn*32 + ni*8 + (lane & 3) * 2;
            const float bb0 = b2[e * HDIM + col];
            const float bb1 = b2[e * HDIM + col + 1];
            #pragma unroll
            for (int half = 0; half < 2; half++) {
                const int lr  = wm*32 + mi*16 + (lane >> 2) + half*8;
                const int pos = m0 + lr;
                if (pos < cnt) {
                    const int pair = lsh[lr];
                    const float gate = g_gate[pair];
                    float2 o;
                    o.x = (acc[mi][ni][half*2 + 0] + bb0) * gate;
                    o.y = (acc[mi][ni][half*2 + 1] + bb1) * gate;
                    *(float2*)(g_y + (size_t)pair * HDIM + col) = o;
                }
            }
        }
    }
}

// ---------------- kernel 4: residual + combine -------------------------------
__global__ __launch_bounds__(256) void combine_kernel(
    const float* __restrict__ x, float* __restrict__ out)
{
    const int tok = blockIdx.x;
    const int tid = threadIdx.x;
    float4 o = ((const float4*)(x + (size_t)tok * HDIM))[tid];
    #pragma unroll
    for (int k = 0; k < TOPK; k++) {
        float4 yv = ((const float4*)(g_y + (size_t)(tok * TOPK + k) * HDIM))[tid];
        o.x += yv.x; o.y += yv.y; o.z += yv.z; o.w += yv.w;
    }
    ((float4*)(out + (size_t)tok * HDIM))[tid] = o;
}

// ---------------- launcher ---------------------------------------------------
extern "C" void kernel_launch(void* const* d_in, const int* in_sizes, int n_in,
                              void* d_out, int out_size)
{
    const float* x  = (const float*)d_in[0];
    const float* ns = (const float*)d_in[1];
    const float* wg = (const float*)d_in[2];
    const float* bg = (const float*)d_in[3];
    const float* w1 = (const float*)d_in[4];
    const float* b1 = (const float*)d_in[5];
    const float* w2 = (const float*)d_in[6];
    const float* b2 = (const float*)d_in[7];
    float* out = (float*)d_out;

    zero_cnt_kernel<<<1, 32>>>();
    router_kernel<<<TOKS, 256>>>(x, ns, wg, bg);
    gemm1_kernel<<<dim3(N2 / BN, TOKS / BM, NEXP), 256>>>(w1, b1);
    gemm2_kernel<<<dim3(HDIM / BN, TOKS / BM, NEXP), 256>>>(w2, b2);
    combine_kernel<<<TOKS, 256>>>(x, out);
}